// round 1
// baseline (speedup 1.0000x reference)
#include <cuda_runtime.h>
#include <cuda_bf16.h>
#include <math.h>

// Problem constants
#define BB 2
#define NN 2048
#define EE 1024
#define HH 16
#define DD 64
#define HD 1024            // H*D
#define MTOT 4096          // B*N

// ---------------------------------------------------------------------------
// Scratch (static device globals — no allocation allowed)
// ---------------------------------------------------------------------------
__device__ float g_Q[MTOT * HD];   // (B*N, H*D)
__device__ float g_K[MTOT * DD];   // (B*N, D)
__device__ float g_V[MTOT * DD];   // (B*N, D)
__device__ float g_Z[MTOT * HD];   // (B*N, H*D)

// ---------------------------------------------------------------------------
// Register-blocked SGEMM: C[M,N] = A[M,K] @ B[K,N] (+ bias)
// Row-major everywhere. M % BM == 0, N % BN == 0, K % BK == 0 assumed.
// ---------------------------------------------------------------------------
template <int BM, int BN, int BK, int TM, int TN, bool BIAS>
__global__ __launch_bounds__((BM / TM) * (BN / TN))
void sgemm_kernel(const float* __restrict__ A, const float* __restrict__ B,
                  const float* __restrict__ bias, float* __restrict__ C,
                  int M, int N, int K)
{
    constexpr int THREADS = (BM / TM) * (BN / TN);
    __shared__ float As[BK][BM];   // transposed A tile
    __shared__ float Bs[BK][BN];

    const int tid  = threadIdx.x;
    const int tx   = tid % (BN / TN);
    const int ty   = tid / (BN / TN);
    const int row0 = blockIdx.y * BM;
    const int col0 = blockIdx.x * BN;

    float acc[TM][TN];
#pragma unroll
    for (int i = 0; i < TM; i++)
#pragma unroll
        for (int j = 0; j < TN; j++) acc[i][j] = 0.0f;

    constexpr int A_VECS     = BM * BK / 4 / THREADS;
    constexpr int B_VECS     = BK * BN / 4 / THREADS;
    constexpr int A_ROW_VECS = BK / 4;
    constexpr int B_ROW_VECS = BN / 4;

    for (int k0 = 0; k0 < K; k0 += BK) {
#pragma unroll
        for (int i = 0; i < A_VECS; i++) {
            int idx = tid + i * THREADS;
            int r   = idx / A_ROW_VECS;
            int c   = (idx % A_ROW_VECS) * 4;
            float4 v = *(const float4*)&A[(size_t)(row0 + r) * K + k0 + c];
            As[c + 0][r] = v.x;
            As[c + 1][r] = v.y;
            As[c + 2][r] = v.z;
            As[c + 3][r] = v.w;
        }
#pragma unroll
        for (int i = 0; i < B_VECS; i++) {
            int idx = tid + i * THREADS;
            int r   = idx / B_ROW_VECS;
            int c   = (idx % B_ROW_VECS) * 4;
            *(float4*)&Bs[r][c] =
                *(const float4*)&B[(size_t)(k0 + r) * N + col0 + c];
        }
        __syncthreads();

#pragma unroll
        for (int kk = 0; kk < BK; kk++) {
            float ra[TM], rb[TN];
#pragma unroll
            for (int i = 0; i < TM; i++) ra[i] = As[kk][ty * TM + i];
#pragma unroll
            for (int j = 0; j < TN; j++) rb[j] = Bs[kk][tx * TN + j];
#pragma unroll
            for (int i = 0; i < TM; i++)
#pragma unroll
                for (int j = 0; j < TN; j++) acc[i][j] += ra[i] * rb[j];
        }
        __syncthreads();
    }

#pragma unroll
    for (int i = 0; i < TM; i++) {
        int row = row0 + ty * TM + i;
#pragma unroll
        for (int j = 0; j < TN; j += 4) {
            int col = col0 + tx * TN + j;
            float4 v;
            v.x = acc[i][j + 0];
            v.y = acc[i][j + 1];
            v.z = acc[i][j + 2];
            v.w = acc[i][j + 3];
            if (BIAS) {
                v.x += bias[col + 0];
                v.y += bias[col + 1];
                v.z += bias[col + 2];
                v.w += bias[col + 3];
            }
            *(float4*)&C[(size_t)row * N + col] = v;
        }
    }
}

// ---------------------------------------------------------------------------
// Causal MQA flash attention.
// grid = (N/Br, B*H), block = Br threads; 1 thread = 1 query row.
// Q: (B*N, H*D) with head h at column h*D.  K,V: (B*N, D).
// Z: (B*N, H*D).
// ---------------------------------------------------------------------------
#define BR 128   // query rows per block (== blockDim.x)
#define BC 64    // key rows per smem tile

__global__ void mqa_attn_kernel(const float* __restrict__ Q,
                                const float* __restrict__ K,
                                const float* __restrict__ V,
                                float* __restrict__ Z)
{
    __shared__ float Ks[BC][DD];
    __shared__ float Vs[BC][DD];

    const int qt  = blockIdx.x;            // query tile
    const int bh  = blockIdx.y;
    const int b   = bh / HH;
    const int h   = bh % HH;
    const int tid = threadIdx.x;
    const int nq  = qt * BR + tid;         // query index within batch

    float q[DD], o[DD];
    const float* Qrow = Q + ((size_t)(b * NN + nq)) * HD + h * DD;
    const float qscale = 0.125f;           // 1/sqrt(64)
#pragma unroll
    for (int d = 0; d < DD; d++) {
        q[d] = Qrow[d] * qscale;
        o[d] = 0.0f;
    }

    float m = -1e30f, l = 0.0f;

    const int klimit = (qt + 1) * BR;      // exclusive key bound for this tile
    for (int k0 = 0; k0 < klimit; k0 += BC) {
        // cooperative tile load (contiguous BC*DD floats)
        const float4* Kt = (const float4*)(K + ((size_t)(b * NN + k0)) * DD);
        const float4* Vt = (const float4*)(V + ((size_t)(b * NN + k0)) * DD);
        float4* Ksv = (float4*)&Ks[0][0];
        float4* Vsv = (float4*)&Vs[0][0];
        for (int i = tid; i < BC * DD / 4; i += BR) {
            Ksv[i] = Kt[i];
            Vsv[i] = Vt[i];
        }
        __syncthreads();

        for (int j0 = 0; j0 < BC; j0 += 8) {
            float s[8];
#pragma unroll
            for (int jj = 0; jj < 8; jj++) {
                float a = 0.0f;
#pragma unroll
                for (int d = 0; d < DD; d++) a += q[d] * Ks[j0 + jj][d];
                int kidx = k0 + j0 + jj;
                s[jj] = (kidx <= nq) ? a : -1e30f;
            }
            float mt = m;
#pragma unroll
            for (int jj = 0; jj < 8; jj++) mt = fmaxf(mt, s[jj]);
            float scale = __expf(m - mt);
            float p[8];
            float lsum = 0.0f;
#pragma unroll
            for (int jj = 0; jj < 8; jj++) {
                p[jj] = __expf(s[jj] - mt);
                lsum += p[jj];
            }
            l = l * scale + lsum;
            m = mt;
#pragma unroll
            for (int d = 0; d < DD; d++) {
                float a = o[d] * scale;
#pragma unroll
                for (int jj = 0; jj < 8; jj++) a += p[jj] * Vs[j0 + jj][d];
                o[d] = a;
            }
        }
        __syncthreads();
    }

    const float inv = 1.0f / l;
    float* Zrow = Z + ((size_t)(b * NN + nq)) * HD + h * DD;
#pragma unroll
    for (int d = 0; d < DD; d += 4) {
        float4 v;
        v.x = o[d + 0] * inv;
        v.y = o[d + 1] * inv;
        v.z = o[d + 2] * inv;
        v.w = o[d + 3] * inv;
        *(float4*)&Zrow[d] = v;
    }
}

// ---------------------------------------------------------------------------
// Launch
// ---------------------------------------------------------------------------
extern "C" void kernel_launch(void* const* d_in, const int* in_sizes, int n_in,
                              void* d_out, int out_size)
{
    const float* X  = (const float*)d_in[0];  // (B,N,E)
    const float* Wq = (const float*)d_in[1];  // (E, H*D)
    const float* Wk = (const float*)d_in[2];  // (E, D)
    const float* Wv = (const float*)d_in[3];  // (E, D)
    const float* Wo = (const float*)d_in[4];  // (H*D, H*D)
    const float* bo = (const float*)d_in[5];  // (H*D,)
    float* out = (float*)d_out;               // (B,N,H*D)

    float *pQ, *pK, *pV, *pZ;
    cudaGetSymbolAddress((void**)&pQ, g_Q);
    cudaGetSymbolAddress((void**)&pK, g_K);
    cudaGetSymbolAddress((void**)&pV, g_V);
    cudaGetSymbolAddress((void**)&pZ, g_Z);

    // Q projection: (4096,1024) @ (1024,1024)
    sgemm_kernel<128, 128, 16, 8, 8, false>
        <<<dim3(HD / 128, MTOT / 128), 256>>>(X, Wq, nullptr, pQ, MTOT, HD, EE);

    // K / V projections: (4096,1024) @ (1024,64)
    sgemm_kernel<128, 64, 16, 8, 4, false>
        <<<dim3(1, MTOT / 128), 256>>>(X, Wk, nullptr, pK, MTOT, DD, EE);
    sgemm_kernel<128, 64, 16, 8, 4, false>
        <<<dim3(1, MTOT / 128), 256>>>(X, Wv, nullptr, pV, MTOT, DD, EE);

    // Causal MQA attention
    mqa_attn_kernel<<<dim3(NN / BR, BB * HH), BR>>>(pQ, pK, pV, pZ);

    // Output projection + bias: (4096,1024) @ (1024,1024) + bo
    sgemm_kernel<128, 128, 16, 8, 8, true>
        <<<dim3(HD / 128, MTOT / 128), 256>>>(pZ, Wo, bo, out, MTOT, HD, HD);
}